// round 17
// baseline (speedup 1.0000x reference)
#include <cuda_runtime.h>
#include <math.h>

#define D_   64
#define T_   128
#define B_   64
#define R_   20
#define SEE_ 10
#define H_   4
#define C_   4
#define NT   1024

typedef unsigned long long ull;

// ---------------- precomputed per-(t,b) data ----------------
__device__ __align__(16) float g_kk [ (size_t)B_*T_*2560 ];
__device__ __align__(16) float g_K2 [ (size_t)B_*T_*2560 ];
__device__ __align__(16) float g_pc [ (size_t)B_*T_*40 ];
__device__ __align__(16) float g_hvS[ (size_t)B_*T_*10*192 ]; // per-item hv (unmasked)
__device__ __align__(16) float g_U  [ (size_t)B_*T_*10*192 ]; // U[item] = hv_sel @ N_bg-half
__device__ __align__(16) float g_up [ (size_t)B_*T_*12 ];     // u_pred per (tb,s)
__device__ __align__(16) float g_bgr[ (size_t)B_*T_*12 ];
__device__ __align__(16) float g_qv [ (size_t)B_*T_*256 ];
__device__ __align__(16) float g_v  [ (size_t)B_*(T_+1)*128 ];
__device__ __align__(16) float g_pr [ (size_t)B_*T_*132 ];
__device__ __align__(16) float g_pn [ (size_t)B_*T_*132 ];
__device__ __align__(16) float g_gxv[ (size_t)B_*T_*192 ];
__device__ __align__(16) float g_pv [ (size_t)B_*T_*4 ];
// ---------------- folded weights ----------------
__device__ __align__(16) float g_Mbg [384*256];
__device__ __align__(16) float g_Mhis[128*256];
__device__ __align__(16) float g_Nbg [384*192];
__device__ __align__(16) float g_Nhis[128*192];
__device__ __align__(16) float g_Nv  [256*192];
__device__ __align__(16) float g_gxc [192];
__device__ __align__(16) float g_wbgp[384];
__device__ __align__(16) float g_whp [128];
__device__ __align__(16) float g_vb1 [256];
__device__ __align__(16) float g_vb2 [256];
__device__            float g_sb  [2];
__device__            float g_dw  [2];

// ---------------- helpers ----------------
__device__ __forceinline__ void ffma2(ull& a, ull x, ull w){
  asm("fma.rn.f32x2 %0, %1, %2, %0;" : "+l"(a) : "l"(x), "l"(w));
}
__device__ __forceinline__ ull pack2(float lo, float hi){
  ull r; asm("mov.b64 %0, {%1,%2};" : "=l"(r) : "f"(lo), "f"(hi)); return r;
}
__device__ __forceinline__ void unpack2(ull a, float& lo, float& hi){
  asm("mov.b64 {%0,%1}, %2;" : "=f"(lo), "=f"(hi) : "l"(a));
}
__device__ __forceinline__ float sigmoidf_(float x){ return 1.0f/(1.0f+expf(-x)); }
__device__ __forceinline__ void cp16(void* sdst, const void* gsrc){
  unsigned sa;
  asm("{.reg .u64 t; cvta.to.shared.u64 t, %1; cvt.u32.u64 %0, t;}" : "=r"(sa) : "l"(sdst));
  asm volatile("cp.async.cg.shared.global [%0], [%1], 16;" :: "r"(sa), "l"(gsrc));
}

// ================= K1: bg gather + kk GEMV + hvS export =================
__global__ void __launch_bounds__(256,4) k1_kernel(
  const int* __restrict__ bg_index, const int* __restrict__ mem_prob_ids,
  const int* __restrict__ mem_resp, const int* __restrict__ mem_concepts,
  const float* __restrict__ states_mem, const float* __restrict__ concept_emb,
  const float* __restrict__ prob_emb,
  const float* __restrict__ W_bg, const float* __restrict__ b_bg)
{
  __shared__ __align__(16) float hvT[2304];
  const int tb = blockIdx.x;
  const int t = tb / B_, b = tb - t*B_;
  const int tid = threadIdx.x;

  for (int i = tid; i < 192*2; i += 256) hvT[(i>>1)*12 + 10 + (i&1)] = 0.f;
  for (int i = tid; i < SEE_*3*D_; i += 256){
    int s = i / (3*D_);
    int k = i - s*3*D_;
    int idx = bg_index[(t*B_ + b)*R_ + s];
    float val;
    if (k < D_){
      val = states_mem[(size_t)idx*D_ + k];
    } else if (k < 2*D_){
      int d = k - D_;
      float ss = 0.f; int cnt = 0;
      #pragma unroll
      for (int c = 0; c < C_; ++c){
        int kc = mem_concepts[(size_t)idx*C_ + c];
        if (kc > 0){ ss += concept_emb[(size_t)(kc-1)*D_ + d]; cnt++; }
      }
      val = ss / (cnt ? (float)cnt : 1.f);
    } else {
      int d  = k - 2*D_;
      int mp = mem_prob_ids[idx];
      val = (mp > 0) ? prob_emb[(size_t)(mp-1)*D_ + d] : 0.f;
    }
    hvT[k*12 + s] = val;
  }
  if (tid < SEE_){
    int idx = bg_index[(t*B_ + b)*R_ + tid];
    g_bgr[(size_t)tb*12 + tid] = (float)mem_resp[idx];
  }
  __syncthreads();

  // item-major hv export for the U GEMM
  for (int i = tid; i < 10*192; i += 256){
    int s = i / 192, k = i - s*192;
    g_hvS[((size_t)tb*10 + s)*192 + k] = hvT[k*12 + s];
  }

  {
    int hh = tid >> 6, d = tid & 63;
    const float* Wg = W_bg + (size_t)hh*(3*D_*D_) + d;
    ull a0=0,a1=0,a2=0,a3=0,a4=0;
    #pragma unroll 2
    for (int k0 = 0; k0 < 192; k0 += 8){
      float w[8];
      #pragma unroll
      for (int u = 0; u < 8; ++u) w[u] = Wg[(size_t)(k0+u)*64];
      #pragma unroll
      for (int u = 0; u < 8; ++u){
        ull ww = pack2(w[u], w[u]);
        const ull* hv = reinterpret_cast<const ull*>(hvT + (k0+u)*12);
        ffma2(a0, hv[0], ww); ffma2(a1, hv[1], ww); ffma2(a2, hv[2], ww);
        ffma2(a3, hv[3], ww); ffma2(a4, hv[4], ww);
      }
    }
    float bb = b_bg[hh*64 + d];
    float lo, hi;
    float* o = g_kk + (size_t)tb*2560 + (size_t)hh*10*64 + d;
    unpack2(a0, lo, hi); o[0*64]=bb+lo; o[1*64]=bb+hi;
    unpack2(a1, lo, hi); o[2*64]=bb+lo; o[3*64]=bb+hi;
    unpack2(a2, lo, hi); o[4*64]=bb+lo; o[5*64]=bb+hi;
    unpack2(a3, lo, hi); o[6*64]=bb+lo; o[7*64]=bb+hi;
    unpack2(a4, lo, hi); o[8*64]=bb+lo; o[9*64]=bb+hi;
  }
}

// ================= K2: v + qv + pred_v =================
__global__ void __launch_bounds__(128,8) k2_kernel(
  const int* __restrict__ prob_id, const int* __restrict__ skills,
  const float* __restrict__ concept_emb, const float* __restrict__ prob_emb,
  const float* __restrict__ W_batch, const float* __restrict__ b_batch,
  const float* __restrict__ W_pred)
{
  __shared__ __align__(16) float v[128];
  __shared__ float red[4];
  const int tb = blockIdx.x;
  const int t = tb / B_, b = tb - t*B_;
  const int tid = threadIdx.x;

  float val;
  if (tid < D_){
    float s = 0.f; int cnt = 0;
    #pragma unroll
    for (int c = 0; c < C_; ++c){
      int k = skills[(t*B_ + b)*C_ + c];
      if (k > 0){ s += concept_emb[(size_t)(k-1)*D_ + tid]; cnt++; }
    }
    val = s / (cnt ? (float)cnt : 1.f);
  } else {
    int pid = prob_id[t*B_ + b];
    val = (pid > 0) ? prob_emb[(size_t)(pid-1)*D_ + (tid - D_)] : 0.f;
  }
  v[tid] = val;
  g_v[((size_t)b*(T_+1) + t + 1)*128 + tid] = val;
  if (t == 0) g_v[((size_t)b*(T_+1))*128 + tid] = 0.f;

  {
    float p = val * W_pred[384 + tid];
    #pragma unroll
    for (int o = 16; o; o >>= 1) p += __shfl_xor_sync(0xffffffffu, p, o);
    if ((tid & 31) == 0) red[tid >> 5] = p;
  }
  __syncthreads();
  if (tid == 0) g_pv[(size_t)tb*4] = red[0]+red[1]+red[2]+red[3];

  int hh = tid >> 5, dp = tid & 31;
  const ull* Wb = reinterpret_cast<const ull*>(W_batch + (size_t)hh*(3*D_*D_)) + dp;
  ull acc = 0;
  const float4* xv = reinterpret_cast<const float4*>(v);
  #pragma unroll 2
  for (int k4 = 0; k4 < 32; ++k4){
    float4 x = xv[k4]; int k = 64 + k4*4;
    ull w0 = Wb[(size_t)(k+0)*32], w1 = Wb[(size_t)(k+1)*32];
    ull w2 = Wb[(size_t)(k+2)*32], w3 = Wb[(size_t)(k+3)*32];
    ffma2(acc, pack2(x.x,x.x), w0); ffma2(acc, pack2(x.y,x.y), w1);
    ffma2(acc, pack2(x.z,x.z), w2); ffma2(acc, pack2(x.w,x.w), w3);
  }
  float lo, hi; unpack2(acc, lo, hi);
  g_qv[(size_t)tb*256 + hh*64 + 2*dp]     = b_batch[hh*64 + 2*dp]     + lo;
  g_qv[(size_t)tb*256 + hh*64 + 2*dp + 1] = b_batch[hh*64 + 2*dp + 1] + hi;
}

// ================= foldM =================
__global__ void __launch_bounds__(256,1) foldM_kernel(
  const float* __restrict__ Wbgint, const float* __restrict__ Whisint,
  const float* __restrict__ Winmap)
{
  __shared__ float xs[16*384];
  const int r0 = blockIdx.x*16;
  const int tid = threadIdx.x;
  for (int i = tid; i < 16*384; i += 256){
    int rr = i/384, j = i - rr*384;
    int gi = r0 + rr;
    xs[i] = (gi < 384) ? Wbgint[(size_t)gi*384 + j] : Whisint[(size_t)(gi-384)*384 + j];
  }
  __syncthreads();
  const int m = tid;
  float acc[16];
  #pragma unroll
  for (int rr = 0; rr < 16; ++rr) acc[rr] = 0.f;
  for (int j = 0; j < 384; ++j){
    float w = Winmap[(size_t)j*256 + m];
    #pragma unroll
    for (int rr = 0; rr < 16; ++rr) acc[rr] += xs[rr*384 + j]*w;
  }
  #pragma unroll
  for (int rr = 0; rr < 16; ++rr){
    int gi = r0 + rr;
    if (gi < 384) g_Mbg[(size_t)gi*256 + m] = acc[rr];
    else          g_Mhis[(size_t)(gi-384)*256 + m] = acc[rr];
  }
}

// ================= foldN =================
__global__ void __launch_bounds__(192,1) foldN_kernel(
  const float* __restrict__ W_ih, const float* __restrict__ Winmap)
{
  __shared__ float xs[16*256];
  const int r0 = blockIdx.x*16;
  const int tid = threadIdx.x;
  for (int i = tid; i < 16*256; i += 192){
    int rr = i >> 8, j = i & 255;
    int gi = r0 + rr;
    float s;
    if (gi < 384)      s = g_Mbg[(size_t)gi*256 + j];
    else if (gi < 512) s = g_Mhis[(size_t)(gi-384)*256 + j];
    else               s = Winmap[(size_t)(gi-128)*256 + j];
    xs[i] = s;
  }
  __syncthreads();
  const int m = tid;
  float acc[16];
  #pragma unroll
  for (int rr = 0; rr < 16; ++rr) acc[rr] = 0.f;
  for (int j = 0; j < 256; ++j){
    float w = W_ih[(size_t)j*192 + m];
    #pragma unroll
    for (int rr = 0; rr < 16; ++rr) acc[rr] += xs[rr*256 + j]*w;
  }
  #pragma unroll
  for (int rr = 0; rr < 16; ++rr){
    int gi = r0 + rr;
    if (gi < 384)      g_Nbg[(size_t)gi*192 + m] = acc[rr];
    else if (gi < 512) g_Nhis[(size_t)(gi-384)*192 + m] = acc[rr];
    else               g_Nv[(size_t)(gi-512)*192 + m] = acc[rr];
  }
}

// ================= foldV =================
__global__ void __launch_bounds__(256,1) foldV_kernel(
  const float* __restrict__ Wbgint, const float* __restrict__ Whisint,
  const float* __restrict__ Winmap, const float* __restrict__ Wpred,
  const float* __restrict__ b_bgint, const float* __restrict__ b_hisint,
  const float* __restrict__ dir_w)
{
  const int blk = blockIdx.x;
  const int tid = threadIdx.x;
  const int lane = tid & 31, wid = tid >> 5;
  if (blk < 48){
    int i = blk*8 + wid;
    float a = 0.f;
    #pragma unroll
    for (int j4 = 0; j4 < 12; ++j4){
      int j = j4*32 + lane;
      a += Wbgint[(size_t)i*384 + j]*Wpred[j];
    }
    #pragma unroll
    for (int o = 16; o; o >>= 1) a += __shfl_xor_sync(0xffffffffu, a, o);
    if (lane == 0) g_wbgp[i] = a;
  } else if (blk < 64){
    int i = (blk-48)*8 + wid;
    float a = 0.f;
    #pragma unroll
    for (int j4 = 0; j4 < 12; ++j4){
      int j = j4*32 + lane;
      a += Whisint[(size_t)i*384 + j]*Wpred[j];
    }
    #pragma unroll
    for (int o = 16; o; o >>= 1) a += __shfl_xor_sync(0xffffffffu, a, o);
    if (lane == 0) g_whp[i] = a;
  } else if (blk == 64 || blk == 65){
    const float* bb = (blk == 64) ? b_bgint : b_hisint;
    float a0=0.f,a1=0.f,a2=0.f,a3=0.f;
    for (int j = 0; j < 384; j += 4){
      a0 += bb[j+0]*Winmap[(size_t)(j+0)*256 + tid];
      a1 += bb[j+1]*Winmap[(size_t)(j+1)*256 + tid];
      a2 += bb[j+2]*Winmap[(size_t)(j+2)*256 + tid];
      a3 += bb[j+3]*Winmap[(size_t)(j+3)*256 + tid];
    }
    float* o = (blk == 64) ? g_vb1 : g_vb2;
    o[tid] = a0+a1+a2+a3;
  } else {
    if (wid < 2){
      const float* bb = (wid == 0) ? b_bgint : b_hisint;
      float a = 0.f;
      #pragma unroll
      for (int j4 = 0; j4 < 12; ++j4){
        int j = j4*32 + lane;
        a += bb[j]*Wpred[j];
      }
      #pragma unroll
      for (int o = 16; o; o >>= 1) a += __shfl_xor_sync(0xffffffffu, a, o);
      if (lane == 0) g_sb[wid] = a;
    } else if (tid == 64){
      float w0 = dir_w[0], w1 = dir_w[1];
      float m  = fmaxf(w0, w1);
      float e0 = expf(w0 - m), e1 = expf(w1 - m);
      g_dw[0] = e0/(e0+e1); g_dw[1] = e1/(e0+e1);
    }
  }
}

// ================= foldGXC =================
__global__ void __launch_bounds__(256,1) foldGXC_kernel(
  const float* __restrict__ W_ih, const float* __restrict__ b_inmap,
  const float* __restrict__ b_ih)
{
  __shared__ float big[256];
  const int tid = threadIdx.x;
  big[tid] = g_dw[0]*g_vb1[tid] + g_dw[1]*g_vb2[tid] + b_inmap[tid];
  __syncthreads();
  if (tid < 192){
    float a0=0.f,a1=0.f,a2=0.f,a3=0.f;
    for (int j = 0; j < 256; j += 4){
      a0 += big[j+0]*W_ih[(size_t)(j+0)*192 + tid];
      a1 += big[j+1]*W_ih[(size_t)(j+1)*192 + tid];
      a2 += big[j+2]*W_ih[(size_t)(j+2)*192 + tid];
      a3 += big[j+3]*W_ih[(size_t)(j+3)*192 + tid];
    }
    g_gxc[tid] = b_ih[tid] + a0+a1+a2+a3;
  }
}

// ================= kU: U[item] = hv_item @ N_bg[half(r)] (GEMM, r-select) =============
__global__ void __launch_bounds__(256,1) kU_kernel()
{
  __shared__ __align__(16) float A[64][36];     // items x k-tile
  __shared__ __align__(16) float Wsm[2][32][68]; // both weight halves
  __shared__ int hisel[64];
  const int itile = blockIdx.x / 3;
  const int ctile = blockIdx.x - itile*3;
  const int i0 = itile*64, c0 = ctile*64;
  const int tid = threadIdx.x;
  const int ty = tid >> 4, tx = tid & 15;

  for (int ii = tid; ii < 64; ii += 256){
    int item = i0 + ii;
    int tb = item/10, s = item - tb*10;
    hisel[ii] = (g_bgr[(size_t)tb*12 + s] > 0.5f) ? 0 : 1;
  }

  ull acc[4][2];
  #pragma unroll
  for (int q = 0; q < 4; ++q){ acc[q][0] = 0; acc[q][1] = 0; }

  for (int kt = 0; kt < 6; ++kt){
    int k0 = kt*32;
    // load A tile: 64 x 32
    #pragma unroll
    for (int q = 0; q < 2; ++q){
      int fid = tid*2 + q;
      int ii = fid >> 3, kq = fid & 7;
      float4 x = *reinterpret_cast<const float4*>(
          g_hvS + (size_t)(i0+ii)*192 + k0 + kq*4);
      *reinterpret_cast<float4*>(&A[ii][kq*4]) = x;
    }
    // load W tiles: both halves 32 x 64
    #pragma unroll
    for (int q = 0; q < 4; ++q){
      int fid = tid*4 + q;
      int half = fid >> 9, rem = fid & 511;
      int kk = rem >> 4, cq = rem & 15;
      float4 x = *reinterpret_cast<const float4*>(
          g_Nbg + (size_t)(half*192 + k0 + kk)*192 + c0 + cq*4);
      *reinterpret_cast<float4*>(&Wsm[half][kk][cq*4]) = x;
    }
    __syncthreads();
    int h0 = hisel[ty*4+0], h1 = hisel[ty*4+1], h2 = hisel[ty*4+2], h3 = hisel[ty*4+3];
    #pragma unroll 4
    for (int kk = 0; kk < 32; ++kk){
      float a0 = A[ty*4+0][kk], a1 = A[ty*4+1][kk];
      float a2 = A[ty*4+2][kk], a3 = A[ty*4+3][kk];
      ulonglong2 w0 = *reinterpret_cast<const ulonglong2*>(&Wsm[h0][kk][tx*4]);
      ulonglong2 w1 = *reinterpret_cast<const ulonglong2*>(&Wsm[h1][kk][tx*4]);
      ulonglong2 w2 = *reinterpret_cast<const ulonglong2*>(&Wsm[h2][kk][tx*4]);
      ulonglong2 w3 = *reinterpret_cast<const ulonglong2*>(&Wsm[h3][kk][tx*4]);
      ull aa0 = pack2(a0,a0), aa1 = pack2(a1,a1), aa2 = pack2(a2,a2), aa3 = pack2(a3,a3);
      ffma2(acc[0][0], aa0, w0.x); ffma2(acc[0][1], aa0, w0.y);
      ffma2(acc[1][0], aa1, w1.x); ffma2(acc[1][1], aa1, w1.y);
      ffma2(acc[2][0], aa2, w2.x); ffma2(acc[2][1], aa2, w2.y);
      ffma2(acc[3][0], aa3, w3.x); ffma2(acc[3][1], aa3, w3.y);
    }
    __syncthreads();
  }
  #pragma unroll
  for (int q = 0; q < 4; ++q){
    float l0,h0,l1,h1;
    unpack2(acc[q][0], l0, h0); unpack2(acc[q][1], l1, h1);
    *reinterpret_cast<float4*>(g_U + (size_t)(i0 + ty*4 + q)*192 + c0 + tx*4)
        = make_float4(l0,h0,l1,h1);
  }
}

// ================= kUP: u_pred[item] = hv_item · wbgp[half] =================
__global__ void __launch_bounds__(256,1) kUP_kernel()
{
  const int tid = threadIdx.x;
  const int lane = tid & 31, wid = tid >> 5;
  int item = blockIdx.x*8 + wid;
  int tb = item/10, s = item - tb*10;
  int base = (g_bgr[(size_t)tb*12 + s] > 0.5f) ? 0 : 192;
  const float* hv = g_hvS + (size_t)item*192;
  float a = 0.f;
  #pragma unroll
  for (int m = 0; m < 6; ++m){
    int j = m*32 + lane;
    a += hv[j]*g_wbgp[base + j];
  }
  #pragma unroll
  for (int o = 16; o; o >>= 1) a += __shfl_xor_sync(0xffffffffu, a, o);
  if (lane == 0) g_up[(size_t)tb*12 + s] = a;
}

// ================= kGXV =================
__global__ void __launch_bounds__(768,1) kGXV_kernel(const int* __restrict__ response)
{
  __shared__ __align__(16) float vs[16*128];
  __shared__ int rf[16];
  const int tb0 = blockIdx.x*16;
  const int tid = threadIdx.x;
  for (int i = tid; i < 16*128; i += 768){
    int ii = i >> 7, c = i & 127;
    int tb = tb0 + ii;
    int t = tb / B_, b = tb - t*B_;
    vs[i] = g_v[((size_t)b*(T_+1) + t + 1)*128 + c];
  }
  if (tid < 16) rf[tid] = response[tb0 + tid];
  __syncthreads();

  int tbs = tid / 48, u = tid - tbs*48;
  const float* vrow = vs + tbs*128;
  int base = rf[tbs] ? 0 : 128;
  const ulonglong2* Np = reinterpret_cast<const ulonglong2*>(g_Nv) + (size_t)base*48 + u;
  ull a0 = 0, a1 = 0;
  #pragma unroll 4
  for (int k = 0; k < 128; ++k){
    float xk = vrow[k];
    ulonglong2 w = Np[(size_t)k*48];
    ull xx = pack2(xk, xk);
    ffma2(a0, xx, w.x); ffma2(a1, xx, w.y);
  }
  float l0,h0,l1,h1; unpack2(a0,l0,h0); unpack2(a1,l1,h1);
  *reinterpret_cast<float4*>(g_gxv + (size_t)(tb0+tbs)*192 + 4*u) = make_float4(l0,h0,l1,h1);
}

// ================= kK2 =================
__global__ void __launch_bounds__(1024,1) kK2_kernel(const float* __restrict__ W_batch)
{
  extern __shared__ float sK2[];
  float* WbT = sK2;
  float* kks = sK2 + 4*4352;
  const int tid = threadIdx.x;

  for (int i = tid; i < 4*64*64; i += 1024){
    int h = i >> 12, rem = i & 4095, e = rem >> 6, d = rem & 63;
    WbT[h*4352 + d*68 + e] = W_batch[(size_t)h*12288 + e*64 + d];
  }
  for (int i = tid; i < 8*2560; i += 1024){
    int tb = i / 2560, r = i - tb*2560;
    kks[i] = g_kk[((size_t)blockIdx.x*8 + tb)*2560 + r];
  }
  __syncthreads();

  {
    int tb = tid >> 7, rem = tid & 127;
    int h = rem >> 5, rem2 = rem & 31;
    int sg = rem2 >> 4, eg = rem2 & 15;
    int p0 = h*10 + sg*5, e0 = eg*4;
    const float* wb = WbT + h*4352 + e0;
    const float* kr = kks + tb*2560 + p0*64;
    float4 acc[5];
    #pragma unroll
    for (int i = 0; i < 5; ++i) acc[i] = make_float4(0.f,0.f,0.f,0.f);
    #pragma unroll 4
    for (int d = 0; d < 64; ++d){
      float4 w = *reinterpret_cast<const float4*>(wb + d*68);
      #pragma unroll
      for (int i = 0; i < 5; ++i){
        float kv = kr[i*64 + d];
        acc[i].x += kv*w.x; acc[i].y += kv*w.y;
        acc[i].z += kv*w.z; acc[i].w += kv*w.w;
      }
    }
    size_t tbg = (size_t)blockIdx.x*8 + tb;
    #pragma unroll
    for (int i = 0; i < 5; ++i)
      *reinterpret_cast<float4*>(g_K2 + tbg*2560 + (p0+i)*64 + e0) = acc[i];
  }
  if (tid < 320){
    int tb = tid / 40, p = tid - tb*40, h = p/10;
    size_t tbg = (size_t)blockIdx.x*8 + tb;
    const float* qv = g_qv + tbg*256 + h*64;
    const float* kr = kks + tb*2560 + p*64;
    float acc = 0.f;
    #pragma unroll 4
    for (int d = 0; d < 64; ++d) acc += qv[d]*kr[d];
    g_pc[tbg*40 + p] = acc;
  }
}

// ================= K3 =================
__global__ void __launch_bounds__(512,1) k3_kernel(const int* __restrict__ response)
{
  extern __shared__ float k3s[];
  float* vv   = k3s;
  float* resp = k3s + (T_+1)*129;
  const int b   = blockIdx.x;
  const int tid = threadIdx.x;
  const int lane = tid & 31, wid = tid >> 5;
  const float inv_s128 = 1.0f/sqrtf(128.0f);

  for (int i = tid; i < (T_+1)*128; i += 512){
    int row = i >> 7, col = i & 127;
    vv[row*129 + col] = g_v[(size_t)b*(T_+1)*128 + i];
  }
  for (int j = tid; j <= T_; j += 512)
    resp[j] = (j == 0) ? 0.f : (float)response[(j-1)*B_ + b];
  __syncthreads();

  for (int t = wid; t < T_; t += 16){
    const float* vt = vv + (t+1)*129;
    float scv[4]; int nj = 0;
    for (int j = lane; j <= t; j += 32){
      const float* vj = vv + j*129;
      float a = 0.f;
      #pragma unroll 4
      for (int k = 0; k < 128; ++k) a += vt[k]*vj[k];
      scv[nj++] = a * inv_s128;
    }
    float mx = -1e30f;
    for (int i = 0; i < nj; ++i) mx = fmaxf(mx, scv[i]);
    #pragma unroll
    for (int o = 16; o; o >>= 1) mx = fmaxf(mx, __shfl_xor_sync(0xffffffffu, mx, o));
    float sum = 0.f;
    for (int i = 0; i < nj; ++i){ scv[i] = expf(scv[i]-mx); sum += scv[i]; }
    #pragma unroll
    for (int o = 16; o; o >>= 1) sum += __shfl_xor_sync(0xffffffffu, sum, o);
    float inv = 1.f/sum;
    int i = 0;
    for (int j = lane; j <= t; j += 32, ++i){
      float p = scv[i]*inv;
      float rb = resp[j];
      g_pr[((size_t)b*T_ + t)*132 + j] = p*rb;
      g_pn[((size_t)b*T_ + t)*132 + j] = p*(1.f-rb);
    }
    for (int j = t+1+lane; j < 132; j += 32){
      g_pr[((size_t)b*T_ + t)*132 + j] = 0.f;
      g_pn[((size_t)b*T_ + t)*132 + j] = 0.f;
    }
  }
}

// ================= K4: sequential recurrence =================
struct __align__(16) SmemSeq {
  alignas(16) float partB[4*192];
  alignas(16) float partD[2*192];
  alignas(16) float h[64];
  alignas(16) float his[128];
  alignas(16) float bgx[192];
  alignas(16) float gh[192];
  alignas(16) float hbufT[64*132];
  alignas(16) float K2s[2][2560];
  alignas(16) float Us[2][1920];
  alignas(16) float pcs[2][40];
  alignas(16) float pr[2][132];
  alignas(16) float pn[2][132];
  alignas(16) float gxv[2][192];
  alignas(16) float pv[2][4];
  alignas(16) float up[2][12];
  alignas(16) float whp_s[128];
  alignas(16) float gxc_s[192];
  alignas(16) float wpredh_s[64];
  alignas(16) float bhh_s[192];
  float logit[40], att[40], ws[12];
  float pred_h, pred_his, predbg;
  float dw0, dw1, sb0, sb1, bp0;
};

__device__ __forceinline__ void do_prefetch(SmemSeq* sm, int b, int tn, int nb,
                                            int idx, int nthr)
{
  size_t tb = (size_t)tn*B_ + b;
  float* d0 = sm->K2s[nb]; const float* s0 = g_K2 + tb*2560;
  float* d1 = sm->Us[nb];  const float* s1 = g_U  + tb*10*192;
  float* d3 = sm->pcs[nb]; const float* s3 = g_pc + tb*40;
  float* d4 = sm->pr[nb];  const float* s4 = g_pr + ((size_t)b*T_ + tn)*132;
  float* d5 = sm->pn[nb];  const float* s5 = g_pn + ((size_t)b*T_ + tn)*132;
  float* d7 = sm->gxv[nb]; const float* s7 = g_gxv + tb*192;
  float* d8 = sm->pv[nb];  const float* s8 = g_pv + tb*4;
  float* d9 = sm->up[nb];  const float* s9 = g_up + tb*12;
  for (int u = idx; u < 640; u += nthr) cp16(d0+4*u, s0+4*u);
  for (int u = idx; u < 480; u += nthr) cp16(d1+4*u, s1+4*u);
  for (int u = idx; u <  10; u += nthr) cp16(d3+4*u, s3+4*u);
  for (int u = idx; u <  33; u += nthr) cp16(d4+4*u, s4+4*u);
  for (int u = idx; u <  33; u += nthr) cp16(d5+4*u, s5+4*u);
  for (int u = idx; u <  48; u += nthr) cp16(d7+4*u, s7+4*u);
  for (int u = idx; u <   1; u += nthr) cp16(d8+4*u, s8+4*u);
  for (int u = idx; u <   3; u += nthr) cp16(d9+4*u, s9+4*u);
}

__device__ __forceinline__ void gemv_seg(const float* __restrict__ W, int rowlen4,
                                         const float* __restrict__ x, int k0, int nk,
                                         int u, float* __restrict__ outp)
{
  const ulonglong2* Wp = reinterpret_cast<const ulonglong2*>(W) + (size_t)k0*rowlen4 + u;
  ull a0 = 0, a1 = 0;
  #pragma unroll 4
  for (int k = 0; k < nk; ++k){
    float xk = x[k0 + k];
    ulonglong2 w = Wp[(size_t)k*rowlen4];
    ull xx = pack2(xk, xk);
    ffma2(a0, xx, w.x);
    ffma2(a1, xx, w.y);
  }
  float l0,h0,l1,h1; unpack2(a0,l0,h0); unpack2(a1,l1,h1);
  *reinterpret_cast<float4*>(outp) = make_float4(l0,h0,l1,h1);
}

__global__ void __launch_bounds__(NT,1) k4_kernel(
  const float* __restrict__ W_pred, const float* __restrict__ b_pred,
  const float* __restrict__ W_hh, const float* __restrict__ b_hh,
  const float* __restrict__ heads_map,
  float* __restrict__ out)
{
  extern __shared__ unsigned char smraw[];
  SmemSeq* sm = reinterpret_cast<SmemSeq*>(smraw);
  const int b    = blockIdx.x;
  const int tid  = threadIdx.x;
  const int lane = tid & 31;
  const int wid  = tid >> 5;
  const float inv_s192 = 1.0f/sqrtf(192.0f);

  if (tid < 64){ sm->h[tid] = 0.f; sm->hbufT[tid*132] = 0.f; }
  if (tid >= 64 && tid < 192) sm->whp_s[tid-64] = g_whp[tid-64];
  if (tid >= 192 && tid < 384) sm->gxc_s[tid-192] = g_gxc[tid-192];
  if (tid >= 384 && tid < 448) sm->wpredh_s[tid-384] = W_pred[512 + (tid-384)];
  if (tid >= 448 && tid < 640) sm->bhh_s[tid-448] = b_hh[tid-448];
  if (tid == 640){
    sm->dw0 = g_dw[0]; sm->dw1 = g_dw[1];
    sm->sb0 = g_sb[0]; sm->sb1 = g_sb[1];
    sm->bp0 = b_pred[0];
  }
  do_prefetch(sm, b, 0, 0, tid, NT);
  asm volatile("cp.async.commit_group;");
  __syncthreads();

  for (int t = 0; t < T_; ++t){
    const int cur = t & 1, nxt = cur ^ 1;
    asm volatile("cp.async.wait_group 0;");
    __syncthreads();

    // ===== P0: logits (0..639) | his (640..767) | prefetch (768..1023) =====
    if (tid < 640){
      int p = tid >> 4, l = tid & 15;
      float4 kv = reinterpret_cast<const float4*>(sm->K2s[cur])[p*16 + l];
      float4 hv = reinterpret_cast<const float4*>(sm->h)[l];
      float acc = kv.x*hv.x + kv.y*hv.y + kv.z*hv.z + kv.w*hv.w;
      #pragma unroll
      for (int o = 8; o; o >>= 1) acc += __shfl_xor_sync(0xffffffffu, acc, o);
      if (l == 0) sm->logit[p] = (acc + sm->pcs[cur][p]) * inv_s192;
    } else if (tid < 768){
      int u = tid - 640, d = u & 63;
      const float4* w4 = reinterpret_cast<const float4*>((u < 64) ? sm->pr[cur] : sm->pn[cur]);
      const float4* h4 = reinterpret_cast<const float4*>(sm->hbufT) + d*33;
      float a0 = 0.f, a1 = 0.f;
      int nj4 = (t >> 2) + 1;
      for (int j4 = 0; j4 < nj4; ++j4){
        float4 ww = w4[j4], hh = h4[j4];
        a0 += ww.x*hh.x + ww.y*hh.y;
        a1 += ww.z*hh.z + ww.w*hh.w;
      }
      sm->his[u] = a0 + a1;
    } else {
      if (t + 1 < T_){
        do_prefetch(sm, b, t+1, nxt, tid-768, 256);
        asm volatile("cp.async.commit_group;");
      }
    }
    __syncthreads();

    // ===== P1: softmax+ws (w0) | pred_h (w1) | pred_his (w2) | W_hh (96..191) | N_his (192..383) =====
    if (wid == 0){
      if (lane < H_){
        float mx = -1e30f;
        #pragma unroll
        for (int s = 0; s < SEE_; ++s) mx = fmaxf(mx, sm->logit[lane*10 + s]);
        float sum = 0.f;
        #pragma unroll
        for (int s = 0; s < SEE_; ++s){
          float e = expf(sm->logit[lane*10 + s] - mx);
          sm->att[lane*10 + s] = e; sum += e;
        }
        float inv = 1.f/sum;
        #pragma unroll
        for (int s = 0; s < SEE_; ++s) sm->att[lane*10 + s] *= inv;
      }
      __syncwarp();
      if (lane < SEE_){
        float a = 0.f;
        #pragma unroll
        for (int hh = 0; hh < H_; ++hh) a += heads_map[hh]*sm->att[hh*10 + lane];
        sm->ws[lane] = a;
      }
    } else if (wid == 1){
      float part = sm->h[lane]*sm->wpredh_s[lane] + sm->h[32+lane]*sm->wpredh_s[32+lane];
      #pragma unroll
      for (int o = 16; o; o >>= 1) part += __shfl_xor_sync(0xffffffffu, part, o);
      if (lane == 0) sm->pred_h = part;
    } else if (wid == 2){
      float part = 0.f;
      #pragma unroll
      for (int j = 0; j < 4; ++j){
        int i = j*32 + lane;
        part += sm->his[i] * sm->whp_s[i];
      }
      #pragma unroll
      for (int o = 16; o; o >>= 1) part += __shfl_xor_sync(0xffffffffu, part, o);
      if (lane == 0) sm->pred_his = part;
    } else if (tid >= 96 && tid < 192){
      int i = tid - 96, seg = i / 48, u = i - seg*48;
      gemv_seg(W_hh, 48, sm->h, seg*32, 32, u, &sm->partD[seg*192 + 4*u]);
    } else if (tid >= 192 && tid < 384){
      int i = tid - 192, seg = i / 48, u = i - seg*48;
      gemv_seg(g_Nhis, 48, sm->his, seg*32, 32, u, &sm->partB[seg*192 + 4*u]);
    }
    __syncthreads();

    // ===== P2: gx_bg (0..191) | gh combine (192..383) | predbg (384..415) =====
    if (tid < 192){
      const float* U = sm->Us[cur];
      float acc = 0.f;
      #pragma unroll
      for (int s = 0; s < SEE_; ++s) acc += sm->ws[s]*U[s*192 + tid];
      sm->bgx[tid] = acc;
    } else if (tid < 384){
      int j = tid - 192;
      sm->gh[j] = sm->bhh_s[j] + sm->partD[j] + sm->partD[192 + j];
    } else if (tid < 416){
      int l = tid - 384;
      float part = (l < SEE_) ? sm->ws[l]*sm->up[cur][l] : 0.f;
      #pragma unroll
      for (int o = 16; o; o >>= 1) part += __shfl_xor_sync(0xffffffffu, part, o);
      if (l == 0) sm->predbg = part;
    }
    __syncthreads();

    // ===== P3: gx combine + GRU (0..63) | out (64) =====
    if (tid < 64){
      int d = tid;
      float sBr=0.f,sBz=0.f,sBn=0.f;
      #pragma unroll
      for (int s = 0; s < 4; ++s){
        const float* pb = sm->partB + s*192;
        sBr += pb[d]; sBz += pb[64+d]; sBn += pb[128+d];
      }
      float gr = sm->gxc_s[d]      + sm->gxv[cur][d]      + sm->dw0*sm->bgx[d]      + sm->dw1*sBr;
      float gz = sm->gxc_s[64+d]   + sm->gxv[cur][64+d]   + sm->dw0*sm->bgx[64+d]   + sm->dw1*sBz;
      float gn = sm->gxc_s[128+d]  + sm->gxv[cur][128+d]  + sm->dw0*sm->bgx[128+d]  + sm->dw1*sBn;
      float r  = sigmoidf_(gr + sm->gh[d]);
      float z  = sigmoidf_(gz + sm->gh[64+d]);
      float n  = tanhf   (gn + r*sm->gh[128+d]);
      float nh = (1.f - z)*n + z*sm->h[d];
      sm->h[d] = nh;
      sm->hbufT[d*132 + (t+1)] = nh;
    } else if (tid == 64){
      out[b*T_ + t] = sm->bp0 + sm->pv[cur][0] + sm->pred_h
                    + sm->dw0*(sm->predbg + sm->sb0)
                    + sm->dw1*(sm->pred_his + sm->sb1);
    }
    __syncthreads();
  }
}

extern "C" void kernel_launch(void* const* d_in, const int* in_sizes, int n_in,
                              void* d_out, int out_size)
{
  (void)in_sizes; (void)n_in; (void)out_size;

  const int*   prob_id      = (const int*)  d_in[0];
  const int*   skills       = (const int*)  d_in[1];
  const int*   response     = (const int*)  d_in[2];
  const int*   bg_index     = (const int*)  d_in[3];
  const int*   mem_prob_ids = (const int*)  d_in[4];
  const int*   mem_resp     = (const int*)  d_in[5];
  const int*   mem_concepts = (const int*)  d_in[6];
  const float* states_mem   = (const float*)d_in[7];
  const float* concept_emb  = (const float*)d_in[8];
  const float* prob_emb     = (const float*)d_in[9];
  const float* W_pred       = (const float*)d_in[10];
  const float* b_pred       = (const float*)d_in[11];
  const float* W_ih         = (const float*)d_in[12];
  const float* W_hh         = (const float*)d_in[13];
  const float* b_ih         = (const float*)d_in[14];
  const float* b_hh         = (const float*)d_in[15];
  const float* W_batch      = (const float*)d_in[16];
  const float* b_batch      = (const float*)d_in[17];
  const float* W_bg         = (const float*)d_in[18];
  const float* b_bg         = (const float*)d_in[19];
  const float* W_bgint      = (const float*)d_in[20];
  const float* b_bgint      = (const float*)d_in[21];
  const float* W_hisint     = (const float*)d_in[22];
  const float* b_hisint     = (const float*)d_in[23];
  const float* W_inmap      = (const float*)d_in[24];
  const float* b_inmap      = (const float*)d_in[25];
  const float* dir_w        = (const float*)d_in[26];
  const float* heads_map    = (const float*)d_in[27];

  k1_kernel<<<T_*B_, 256>>>(bg_index, mem_prob_ids, mem_resp, mem_concepts,
                            states_mem, concept_emb, prob_emb, W_bg, b_bg);
  k2_kernel<<<T_*B_, 128>>>(prob_id, skills, concept_emb, prob_emb,
                            W_batch, b_batch, W_pred);
  foldM_kernel<<<32, 256>>>(W_bgint, W_hisint, W_inmap);
  foldV_kernel<<<67, 256>>>(W_bgint, W_hisint, W_inmap, W_pred,
                            b_bgint, b_hisint, dir_w);
  foldN_kernel<<<48, 192>>>(W_ih, W_inmap);
  foldGXC_kernel<<<1, 256>>>(W_ih, b_inmap, b_ih);

  kU_kernel<<<(T_*B_*10/64)*3, 256>>>();
  kUP_kernel<<<T_*B_*10/8, 256>>>();

  int kK2smem = (4*4352 + 8*2560) * (int)sizeof(float);
  cudaFuncSetAttribute(kK2_kernel, cudaFuncAttributeMaxDynamicSharedMemorySize, kK2smem);
  kK2_kernel<<<T_*B_/8, 1024, kK2smem>>>(W_batch);

  int k3smem = ((T_+1)*129 + 132) * (int)sizeof(float);
  cudaFuncSetAttribute(k3_kernel, cudaFuncAttributeMaxDynamicSharedMemorySize, k3smem);
  k3_kernel<<<B_, 512, k3smem>>>(response);

  kGXV_kernel<<<T_*B_/16, 768>>>(response);

  cudaFuncSetAttribute(k4_kernel, cudaFuncAttributeMaxDynamicSharedMemorySize,
                       (int)sizeof(SmemSeq));
  k4_kernel<<<B_, NT, sizeof(SmemSeq)>>>(
    W_pred, b_pred, W_hh, b_hh, heads_map, (float*)d_out);
}